// round 1
// baseline (speedup 1.0000x reference)
#include <cuda_runtime.h>

// SSIM, fused single pass.
// Images: [16, 3, 512, 512] fp32 in [0,1). Window 11x11 valid -> 502x502 map.
// Output: [16] per-batch mean over (channel, spatial).

#define IMG_H 512
#define IMG_W 512
#define OUT_HW 502          // 512 - 11 + 1
#define TH 32               // output tile rows per block
#define TW 64               // output tile cols per block
#define RH (TH + 10)        // 42 input rows staged
#define RW (TW + 10)        // 74 input cols staged
#define STR 75              // padded smem stride (odd mod 32, 75%8=3 for float4)
#define NTHREADS 256

#define C1 (0.01f * 0.01f)
#define C2 (0.03f * 0.03f)

// smem layout (dynamic):
//   float  sx[RH][STR]           42*75*4  = 12600 B
//   float  sy[RH][STR]                    = 12600 B
//   float4 va[TH][STR]           32*75*16 = 38400 B   (S1,S2,S11,S22)
//   float  vb[TH][STR]           32*75*4  =  9600 B   (S12)
#define SMEM_BYTES (RH*STR*4*2 + TH*STR*16 + TH*STR*4)

__global__ void ssim_zero_kernel(float* __restrict__ out, int n) {
    int i = blockIdx.x * blockDim.x + threadIdx.x;
    if (i < n) out[i] = 0.0f;
}

__global__ __launch_bounds__(NTHREADS, 3)
void ssim_kernel(const float* __restrict__ img1,
                 const float* __restrict__ img2,
                 float* __restrict__ out)
{
    extern __shared__ char smem_raw[];
    float*  sx = (float*)smem_raw;
    float*  sy = sx + RH * STR;
    float4* va = (float4*)(sy + RH * STR);      // offset 25200, 16B aligned
    float*  vb = (float*)(va + TH * STR);

    const int tid  = threadIdx.x;
    const int img  = blockIdx.z;                // 0..47  (batch*3 + channel)
    const int r0   = blockIdx.y * TH;           // output tile origin row
    const int c0   = blockIdx.x * TW;           // output tile origin col

    const float* p1 = img1 + (size_t)img * IMG_H * IMG_W;
    const float* p2 = img2 + (size_t)img * IMG_H * IMG_W;

    // ---------------- Phase 1: stage clipped inputs into smem ----------------
    // Region rows r0..r0+41, cols c0..c0+73, clamped to image bounds.
    // Clamped (out-of-range) entries feed only tile positions that are
    // guarded out in phase 3, so clamping is safe.
    #pragma unroll 4
    for (int i = tid; i < RH * RW; i += NTHREADS) {
        int r = i / RW;
        int c = i - r * RW;
        int gr = min(r0 + r, IMG_H - 1);
        int gc = min(c0 + c, IMG_W - 1);
        size_t gi = (size_t)gr * IMG_W + gc;
        float x = p1[gi];
        float y = p2[gi];
        x = fminf(fmaxf(x, 0.0f), 1.0f);
        y = fminf(fmaxf(y, 0.0f), 1.0f);
        sx[r * STR + c] = x;
        sy[r * STR + c] = y;
    }
    __syncthreads();

    // ---------------- Phase 2: vertical 11-row sliding sums ----------------
    // 148 active threads: column cc in [0,74), row-half in {0,1} (16 rows each).
    if (tid < 2 * RW) {
        const int half   = (tid >= RW) ? 1 : 0;
        const int cc     = half ? (tid - RW) : tid;
        const int rstart = half * (TH / 2);     // 0 or 16

        float s1 = 0.f, s2 = 0.f, s11 = 0.f, s22 = 0.f, s12 = 0.f;
        #pragma unroll
        for (int k = 0; k < 10; k++) {
            float x = sx[(rstart + k) * STR + cc];
            float y = sy[(rstart + k) * STR + cc];
            s1 += x; s2 += y;
            s11 += x * x; s22 += y * y; s12 += x * y;
        }
        #pragma unroll
        for (int rr = rstart; rr < rstart + TH / 2; rr++) {
            float x = sx[(rr + 10) * STR + cc];
            float y = sy[(rr + 10) * STR + cc];
            s1 += x; s2 += y;
            s11 += x * x; s22 += y * y; s12 += x * y;

            va[rr * STR + cc] = make_float4(s1, s2, s11, s22);
            vb[rr * STR + cc] = s12;

            x = sx[rr * STR + cc];
            y = sy[rr * STR + cc];
            s1 -= x; s2 -= y;
            s11 -= x * x; s22 -= y * y; s12 -= x * y;
        }
    }
    __syncthreads();

    // ---------------- Phase 3: horizontal 11-col sliding sums + SSIM --------
    // warp w owns columns [w*8, w*8+8); lane = output row rr.
    // Subtract side served from a register ring (the first 8 warmup reads).
    const int warp  = tid >> 5;
    const int lane  = tid & 31;
    const int cbase = warp * 8;
    const int rr    = lane;

    const float4* vrow  = va + rr * STR;
    const float*  vbrow = vb + rr * STR;

    float4 W4[8];
    float  W1[8];
    float a1 = 0.f, a2 = 0.f, a11 = 0.f, a22 = 0.f, a12 = 0.f;

    #pragma unroll
    for (int k = 0; k < 10; k++) {
        float4 t  = vrow[cbase + k];
        float  tb = vbrow[cbase + k];
        if (k < 8) { W4[k] = t; W1[k] = tb; }
        a1 += t.x; a2 += t.y; a11 += t.z; a22 += t.w; a12 += tb;
    }

    const bool  rowok = (r0 + rr) < OUT_HW;
    const float inv   = 1.0f / 121.0f;
    float local = 0.0f;

    #pragma unroll
    for (int c = 0; c < 8; c++) {
        float4 t  = vrow[cbase + c + 10];
        float  tb = vbrow[cbase + c + 10];
        a1 += t.x; a2 += t.y; a11 += t.z; a22 += t.w; a12 += tb;

        if (rowok && (c0 + cbase + c) < OUT_HW) {
            float mu1 = a1 * inv;
            float mu2 = a2 * inv;
            float mu1sq  = mu1 * mu1;
            float mu2sq  = mu2 * mu2;
            float mu1mu2 = mu1 * mu2;
            float v1  = fmaf(a11, inv, -mu1sq);
            float v2  = fmaf(a22, inv, -mu2sq);
            float v12 = fmaf(a12, inv, -mu1mu2);
            float num = (2.0f * mu1mu2 + C1) * (2.0f * v12 + C2);
            float den = (mu1sq + mu2sq + C1) * (v1 + v2 + C2);
            local += num / den;
        }

        a1 -= W4[c].x; a2 -= W4[c].y; a11 -= W4[c].z; a22 -= W4[c].w;
        a12 -= W1[c];
    }

    // ---------------- Reduction: warp shuffle -> block -> atomic -----------
    #pragma unroll
    for (int o = 16; o > 0; o >>= 1)
        local += __shfl_xor_sync(0xffffffffu, local, o);

    __shared__ float red[NTHREADS / 32];
    if (lane == 0) red[warp] = local;
    __syncthreads();

    if (tid == 0) {
        float s = 0.f;
        #pragma unroll
        for (int w = 0; w < NTHREADS / 32; w++) s += red[w];
        // mean over 3 channels * 502*502 spatial
        const float scale = 1.0f / (3.0f * (float)OUT_HW * (float)OUT_HW);
        atomicAdd(out + img / 3, s * scale);
    }
}

extern "C" void kernel_launch(void* const* d_in, const int* in_sizes, int n_in,
                              void* d_out, int out_size) {
    const float* img1 = (const float*)d_in[0];
    const float* img2 = (const float*)d_in[1];
    float* out = (float*)d_out;

    // Idempotent, capture-safe (not a stream op, no allocation).
    cudaFuncSetAttribute(ssim_kernel,
                         cudaFuncAttributeMaxDynamicSharedMemorySize,
                         SMEM_BYTES);

    ssim_zero_kernel<<<1, 32>>>(out, out_size);

    dim3 grid((OUT_HW + TW - 1) / TW,   // 8
              (OUT_HW + TH - 1) / TH,   // 16
              48);                      // 16 batches * 3 channels
    ssim_kernel<<<grid, NTHREADS, SMEM_BYTES>>>(img1, img2, out);
}

// round 6
// speedup vs baseline: 1.2285x; 1.2285x over previous
#include <cuda_runtime.h>

// SSIM fused single pass, v2.1.
// [16,3,512,512] fp32 -> 11x11 valid SSIM map -> per-batch mean [16].
//
// Per block (tile = 32 out rows x 70 out cols):
//   Phase A: vertical 11-row sliding sums of 5 moments streamed directly
//            from gmem (coalesced; leave-side re-reads hit L1). 4 groups of
//            80 threads; packed f32x2 math for (S1,S2) and (S11,S22).
//   Phase B: horizontal 11-col sliding sums + SSIM. 10 warps x 7 cols,
//            lane = output row; vb subtract side from a register ring.

#define IMG_H 512
#define IMG_W 512
#define OUT_HW 502
#define TH 32
#define TW 70
#define RW 80                 // staged cols = TW + 10
#define VSTR 81               // smem stride (81%8==1 -> conflict-free float4)
#define NTH 320
#define NWARP (NTH / 32)
#define CPW 7                 // output cols per warp (10*7 = 70)

#define C1c (0.01f * 0.01f)
#define C2c (0.03f * 0.03f)

#define SMEM_BYTES (TH * VSTR * (16 + 4))   // va(float4) + vb(float) = 51840

// ---- packed f32x2 helpers (Blackwell) ----
__device__ __forceinline__ unsigned long long f2pack(float lo, float hi) {
    unsigned long long r;
    asm("mov.b64 %0, {%1, %2};" : "=l"(r) : "f"(lo), "f"(hi));
    return r;
}
__device__ __forceinline__ void f2unpack(unsigned long long p, float& lo, float& hi) {
    asm("mov.b64 {%0, %1}, %2;" : "=f"(lo), "=f"(hi) : "l"(p));
}
__device__ __forceinline__ unsigned long long f2add(unsigned long long a, unsigned long long b) {
    unsigned long long r;
    asm("add.rn.f32x2 %0, %1, %2;" : "=l"(r) : "l"(a), "l"(b));
    return r;
}
__device__ __forceinline__ unsigned long long f2mul(unsigned long long a, unsigned long long b) {
    unsigned long long r;
    asm("mul.rn.f32x2 %0, %1, %2;" : "=l"(r) : "l"(a), "l"(b));
    return r;
}
__device__ __forceinline__ unsigned long long f2fma(unsigned long long a, unsigned long long b,
                                                    unsigned long long c) {
    unsigned long long r;
    asm("fma.rn.f32x2 %0, %1, %2, %3;" : "=l"(r) : "l"(a), "l"(b), "l"(c));
    return r;
}

__global__ void ssim_zero_kernel(float* __restrict__ out, int n) {
    int i = blockIdx.x * blockDim.x + threadIdx.x;
    if (i < n) out[i] = 0.0f;
}

__global__ __launch_bounds__(NTH, 4)
void ssim_kernel(const float* __restrict__ img1,
                 const float* __restrict__ img2,
                 float* __restrict__ out)
{
    extern __shared__ char smem_raw[];
    float4* va = (float4*)smem_raw;                 // [TH][VSTR] (S1,S2,S11,S22)
    float*  vb = (float*)(va + TH * VSTR);          // [TH][VSTR] (S12)
    __shared__ float red[NWARP];

    const int tid = threadIdx.x;
    const int img = blockIdx.z;                     // batch*3 + channel
    const int r0  = blockIdx.y * TH;
    const int c0  = blockIdx.x * TW;

    const float* p1 = img1 + (size_t)img * IMG_H * IMG_W;
    const float* p2 = img2 + (size_t)img * IMG_H * IMG_W;

    const unsigned long long NEG1 = f2pack(-1.0f, -1.0f);

    // ---------------- Phase A: vertical sliding sums (gmem -> smem) --------
    {
        const int g   = tid / RW;                   // row group 0..3
        const int cc  = tid - g * RW;               // staged col 0..79
        const int gr0 = r0 + g * 8;                 // first leave row
        const int gc  = min(c0 + cc, IMG_W - 1);    // col clamp (once)

        unsigned long long S = 0ull, Q = 0ull;      // (s1,s2), (s11,s22)
        float s12 = 0.0f;

        if (gr0 + 17 < IMG_H) {
            // fast path: all 18 rows in range
            const float* q1 = p1 + (size_t)gr0 * IMG_W + gc;
            const float* q2 = p2 + (size_t)gr0 * IMG_W + gc;
            #pragma unroll
            for (int k = 0; k < 10; k++) {
                float x = __saturatef(q1[k * IMG_W]);
                float y = __saturatef(q2[k * IMG_W]);
                unsigned long long p = f2pack(x, y);
                S = f2add(S, p);
                Q = f2fma(p, p, Q);
                s12 = fmaf(x, y, s12);
            }
            #pragma unroll
            for (int i = 0; i < 8; i++) {
                float x = __saturatef(q1[(i + 10) * IMG_W]);
                float y = __saturatef(q2[(i + 10) * IMG_W]);
                unsigned long long p = f2pack(x, y);
                S = f2add(S, p);
                Q = f2fma(p, p, Q);
                s12 = fmaf(x, y, s12);

                float s1, s2, s11, s22;
                f2unpack(S, s1, s2);
                f2unpack(Q, s11, s22);
                const int row = g * 8 + i;
                va[row * VSTR + cc] = make_float4(s1, s2, s11, s22);
                vb[row * VSTR + cc] = s12;

                x = __saturatef(q1[i * IMG_W]);
                y = __saturatef(q2[i * IMG_W]);
                p = f2pack(x, y);
                S = f2fma(p, NEG1, S);
                Q = f2fma(f2mul(p, p), NEG1, Q);
                s12 = fmaf(x, -y, s12);
            }
        } else {
            // bottom-edge tile: clamp rows per load (clamped cells feed only
            // guarded-out outputs)
            #pragma unroll
            for (int k = 0; k < 10; k++) {
                size_t gi = (size_t)min(gr0 + k, IMG_H - 1) * IMG_W + gc;
                float x = __saturatef(p1[gi]);
                float y = __saturatef(p2[gi]);
                unsigned long long p = f2pack(x, y);
                S = f2add(S, p);
                Q = f2fma(p, p, Q);
                s12 = fmaf(x, y, s12);
            }
            #pragma unroll
            for (int i = 0; i < 8; i++) {
                size_t gi = (size_t)min(gr0 + i + 10, IMG_H - 1) * IMG_W + gc;
                float x = __saturatef(p1[gi]);
                float y = __saturatef(p2[gi]);
                unsigned long long p = f2pack(x, y);
                S = f2add(S, p);
                Q = f2fma(p, p, Q);
                s12 = fmaf(x, y, s12);

                float s1, s2, s11, s22;
                f2unpack(S, s1, s2);
                f2unpack(Q, s11, s22);
                const int row = g * 8 + i;
                va[row * VSTR + cc] = make_float4(s1, s2, s11, s22);
                vb[row * VSTR + cc] = s12;

                gi = (size_t)min(gr0 + i, IMG_H - 1) * IMG_W + gc;
                x = __saturatef(p1[gi]);
                y = __saturatef(p2[gi]);
                p = f2pack(x, y);
                S = f2fma(p, NEG1, S);
                Q = f2fma(f2mul(p, p), NEG1, Q);
                s12 = fmaf(x, -y, s12);
            }
        }
    }
    __syncthreads();

    // ---------------- Phase B: horizontal sliding sums + SSIM --------------
    const int warp  = tid >> 5;
    const int lane  = tid & 31;
    const int cbase = warp * CPW;

    const float4* vr  = va + lane * VSTR + cbase;
    const float*  vbr = vb + lane * VSTR + cbase;

    unsigned long long A = 0ull, B = 0ull;          // (a1,a2), (a11,a22)
    float a12 = 0.0f;
    float ringb[CPW];                               // vb subtract-side ring

    #pragma unroll
    for (int k = 0; k < 10; k++) {
        float4 t = vr[k];
        float  b = vbr[k];
        if (k < CPW) ringb[k] = b;
        A = f2add(A, f2pack(t.x, t.y));
        B = f2add(B, f2pack(t.z, t.w));
        a12 += b;
    }

    const bool rowok = (r0 + lane) < OUT_HW;
    const float inv  = 1.0f / 121.0f;
    float local = 0.0f;

    #pragma unroll
    for (int j = 0; j < CPW; j++) {
        float4 t = vr[j + 10];
        A = f2add(A, f2pack(t.x, t.y));
        B = f2add(B, f2pack(t.z, t.w));
        a12 += vbr[j + 10];

        if (rowok && (c0 + cbase + j) < OUT_HW) {
            float a1, a2, a11, a22;
            f2unpack(A, a1, a2);
            f2unpack(B, a11, a22);
            float mu1 = a1 * inv;
            float mu2 = a2 * inv;
            float mu1sq  = mu1 * mu1;
            float mu2sq  = mu2 * mu2;
            float mu12   = mu1 * mu2;
            float v1  = fmaf(a11, inv, -mu1sq);
            float v2  = fmaf(a22, inv, -mu2sq);
            float v12 = fmaf(a12, inv, -mu12);
            float num = (2.0f * mu12 + C1c) * (2.0f * v12 + C2c);
            float den = (mu1sq + mu2sq + C1c) * (v1 + v2 + C2c);
            local += __fdividef(num, den);
        }

        float4 s = vr[j];
        A = f2fma(f2pack(s.x, s.y), NEG1, A);
        B = f2fma(f2pack(s.z, s.w), NEG1, B);
        a12 -= ringb[j];
    }

    // ---------------- Reduction ----------------
    #pragma unroll
    for (int o = 16; o > 0; o >>= 1)
        local += __shfl_xor_sync(0xffffffffu, local, o);

    if (lane == 0) red[warp] = local;
    __syncthreads();

    if (tid == 0) {
        float s = 0.0f;
        #pragma unroll
        for (int w = 0; w < NWARP; w++) s += red[w];
        const float scale = 1.0f / (3.0f * (float)OUT_HW * (float)OUT_HW);
        atomicAdd(out + img / 3, s * scale);
    }
}

extern "C" void kernel_launch(void* const* d_in, const int* in_sizes, int n_in,
                              void* d_out, int out_size) {
    const float* img1 = (const float*)d_in[0];
    const float* img2 = (const float*)d_in[1];
    float* out = (float*)d_out;

    cudaFuncSetAttribute(ssim_kernel,
                         cudaFuncAttributeMaxDynamicSharedMemorySize,
                         SMEM_BYTES);

    ssim_zero_kernel<<<1, 32>>>(out, out_size);

    dim3 grid((OUT_HW + TW - 1) / TW,   // 8
              (OUT_HW + TH - 1) / TH,   // 16
              48);                      // 16 batches * 3 channels
    ssim_kernel<<<grid, NTH, SMEM_BYTES>>>(img1, img2, out);
}